// round 4
// baseline (speedup 1.0000x reference)
#include <cuda_runtime.h>

// cov = M M^T with m_ik = R(q)_ik * s_k, computed exactly like the reference.
//
// Memory-bound: 64 B per gaussian. R2 changes vs R1:
//  - 4 elements per thread (block covers 1024 gaussians): MLP ~7 per thread,
//    4x fewer __syncthreads per element.
//  - all loads/stores remain fully coalesced 128-bit via smem staging;
//    stride-9 / stride-3 smem layouts are odd -> bank-conflict-free.

#define TPB 256
#define EPT 4
#define BLK (TPB * EPT)   // 1024 elements per block

__global__ __launch_bounds__(TPB) void cov_kernel(
    const float4* __restrict__ quat,   // [N] of (w,x,y,z)
    const float*  __restrict__ scales, // [N*3]
    float*        __restrict__ out,    // [N*9]
    int n)
{
    __shared__ float s_sc[BLK * 3];    // 12 KB
    __shared__ float s_out[BLK * 9];   // 36 KB

    const int tid = threadIdx.x;
    const size_t base = (size_t)blockIdx.x * BLK;
    const int valid = min(BLK, n - (int)base);

    // ---- stage scales: coalesced float4 loads ----
    if (valid == BLK) {
        const float4* sc4 = reinterpret_cast<const float4*>(scales + base * 3);
        float4* dst = reinterpret_cast<float4*>(s_sc);
        #pragma unroll
        for (int k = 0; k < 3; k++)                 // 768 float4 total
            dst[tid + k * TPB] = sc4[tid + k * TPB];
    } else {
        for (int j = tid; j < valid * 3; j += TPB)
            s_sc[j] = scales[base * 3 + j];
    }

    // ---- front-batched quat loads (issued before the barrier) ----
    float4 q[EPT];
    #pragma unroll
    for (int k = 0; k < EPT; k++) {
        int e = tid + k * TPB;
        if (e < valid) q[k] = quat[base + e];
    }

    __syncthreads();

    // ---- compute + stage outputs ----
    #pragma unroll
    for (int k = 0; k < EPT; k++) {
        int e = tid + k * TPB;
        if (e < valid) {
            float w = q[k].x, x = q[k].y, y = q[k].z, z = q[k].w;

            float xx = x * x, yy = y * y, zz = z * z;
            float xy = x * y, xz = x * z, yz = y * z;
            float wx = w * x, wy = w * y, wz = w * z;

            float r00 = 1.0f - 2.0f * (yy + zz);
            float r01 = 2.0f * (xy - wz);
            float r02 = 2.0f * (xz + wy);
            float r10 = 2.0f * (xy + wz);
            float r11 = 1.0f - 2.0f * (xx + zz);
            float r12 = 2.0f * (yz - wx);
            float r20 = 2.0f * (xz - wy);
            float r21 = 2.0f * (yz + wx);
            float r22 = 1.0f - 2.0f * (xx + yy);

            float sx = s_sc[e * 3 + 0];
            float sy = s_sc[e * 3 + 1];
            float sz = s_sc[e * 3 + 2];

            float m00 = r00 * sx, m01 = r01 * sy, m02 = r02 * sz;
            float m10 = r10 * sx, m11 = r11 * sy, m12 = r12 * sz;
            float m20 = r20 * sx, m21 = r21 * sy, m22 = r22 * sz;

            float c00 = m00 * m00 + m01 * m01 + m02 * m02;
            float c01 = m00 * m10 + m01 * m11 + m02 * m12;
            float c02 = m00 * m20 + m01 * m21 + m02 * m22;
            float c11 = m10 * m10 + m11 * m11 + m12 * m12;
            float c12 = m10 * m20 + m11 * m21 + m12 * m22;
            float c22 = m20 * m20 + m21 * m21 + m22 * m22;

            float* o = &s_out[e * 9];   // stride 9: conflict-free
            o[0] = c00; o[1] = c01; o[2] = c02;
            o[3] = c01; o[4] = c11; o[5] = c12;
            o[6] = c02; o[7] = c12; o[8] = c22;
        }
    }

    __syncthreads();

    // ---- coalesced write-out: float4 bulk + scalar tail ----
    const size_t out_base = base * 9;
    const int nf  = valid * 9;
    const int nf4 = nf / 4;                  // full block: 2304 float4 = 9 per thread
    float4* o4 = reinterpret_cast<float4*>(out + out_base); // 16B aligned (base*36 B)
    const float4* so4 = reinterpret_cast<const float4*>(s_out);
    for (int k = tid; k < nf4; k += TPB)
        o4[k] = so4[k];
    for (int k = nf4 * 4 + tid; k < nf; k += TPB)
        out[out_base + k] = s_out[k];
}

extern "C" void kernel_launch(void* const* d_in, const int* in_sizes, int n_in,
                              void* d_out, int out_size) {
    const float4* quat   = (const float4*)d_in[0]; // quaternions [N,4]
    const float*  scales = (const float*) d_in[1]; // scales [N,3]
    float* out = (float*)d_out;                    // cov [N,3,3]

    int n = in_sizes[0] / 4;
    int grid = (n + BLK - 1) / BLK;
    cov_kernel<<<grid, TPB>>>(quat, scales, out, n);
}

// round 5
// speedup vs baseline: 1.0751x; 1.0751x over previous
#include <cuda_runtime.h>

// cov = M M^T with m_ik = R(q)_ik * s_k, identical math to the reference.
//
// Memory-bound: 64 B/gaussian, 256 MB total — pure HBM stream.
// R3 design:
//  - EPT=2, 18 KB smem -> 8 blocks/SM -> ~100% occupancy (R2 was 46%).
//  - single __syncthreads: scales loaded per-thread directly (__ldcs,
//    stride-12B: all fetched sectors fully consumed warp-wide).
//  - output staged in smem (stride-9 = conflict-free) then written as
//    fully-coalesced float4 streaming stores (__stcs, evict-first) so the
//    one-pass 256 MB stream doesn't thrash L2.

#define TPB 256
#define EPT 2
#define BLK (TPB * EPT)   // 512 elements per block

__global__ __launch_bounds__(TPB) void cov_kernel(
    const float4* __restrict__ quat,   // [N] of (w,x,y,z)
    const float*  __restrict__ scales, // [N*3]
    float*        __restrict__ out,    // [N*9]
    int n)
{
    __shared__ float s_out[BLK * 9];   // 18 KB

    const int tid = threadIdx.x;
    const size_t base = (size_t)blockIdx.x * BLK;
    const int valid = min(BLK, n - (int)base);

    #pragma unroll
    for (int k = 0; k < EPT; k++) {
        int e = tid + k * TPB;
        if (e < valid) {
            float4 q = __ldcs(&quat[base + e]);
            const float* sp = scales + (base + e) * 3;
            float sx = __ldcs(sp + 0);
            float sy = __ldcs(sp + 1);
            float sz = __ldcs(sp + 2);

            float w = q.x, x = q.y, y = q.z, z = q.w;

            float xx = x * x, yy = y * y, zz = z * z;
            float xy = x * y, xz = x * z, yz = y * z;
            float wx = w * x, wy = w * y, wz = w * z;

            float r00 = 1.0f - 2.0f * (yy + zz);
            float r01 = 2.0f * (xy - wz);
            float r02 = 2.0f * (xz + wy);
            float r10 = 2.0f * (xy + wz);
            float r11 = 1.0f - 2.0f * (xx + zz);
            float r12 = 2.0f * (yz - wx);
            float r20 = 2.0f * (xz - wy);
            float r21 = 2.0f * (yz + wx);
            float r22 = 1.0f - 2.0f * (xx + yy);

            float m00 = r00 * sx, m01 = r01 * sy, m02 = r02 * sz;
            float m10 = r10 * sx, m11 = r11 * sy, m12 = r12 * sz;
            float m20 = r20 * sx, m21 = r21 * sy, m22 = r22 * sz;

            float c00 = m00 * m00 + m01 * m01 + m02 * m02;
            float c01 = m00 * m10 + m01 * m11 + m02 * m12;
            float c02 = m00 * m20 + m01 * m21 + m02 * m22;
            float c11 = m10 * m10 + m11 * m11 + m12 * m12;
            float c12 = m10 * m20 + m11 * m21 + m12 * m22;
            float c22 = m20 * m20 + m21 * m21 + m22 * m22;

            float* o = &s_out[e * 9];   // stride 9: bank-conflict-free
            o[0] = c00; o[1] = c01; o[2] = c02;
            o[3] = c01; o[4] = c11; o[5] = c12;
            o[6] = c02; o[7] = c12; o[8] = c22;
        }
    }

    __syncthreads();

    // ---- coalesced streaming write-out: float4 bulk + scalar tail ----
    const size_t out_base = base * 9;
    const int nf  = valid * 9;
    const int nf4 = nf / 4;                  // full block: 1152 float4
    float4* o4 = reinterpret_cast<float4*>(out + out_base); // 16B aligned (base*36 B)
    const float4* so4 = reinterpret_cast<const float4*>(s_out);
    #pragma unroll 3
    for (int k = tid; k < nf4; k += TPB)
        __stcs(&o4[k], so4[k]);
    for (int k = nf4 * 4 + tid; k < nf; k += TPB)
        __stcs(&out[out_base + k], s_out[k]);
}

extern "C" void kernel_launch(void* const* d_in, const int* in_sizes, int n_in,
                              void* d_out, int out_size) {
    const float4* quat   = (const float4*)d_in[0]; // quaternions [N,4]
    const float*  scales = (const float*) d_in[1]; // scales [N,3]
    float* out = (float*)d_out;                    // cov [N,3,3]

    int n = in_sizes[0] / 4;
    int grid = (n + BLK - 1) / BLK;
    cov_kernel<<<grid, TPB>>>(quat, scales, out, n);
}